// round 12
// baseline (speedup 1.0000x reference)
#include <cuda_runtime.h>
#include <cuda_bf16.h>
#include <cstdint>

#define NN 50000
#define DD 128
#define EE 1600000
#define ET (EE + NN)
#define LL 3
#define SLOPE 0.2f
#define NBLK_SCAN ((NN + 1023) / 1024)
#define KC 32
#define AST 20
#define BM 64
#define NBLK_GEMM ((NN + BM - 1) / BM)
#define NBLK_AGG ((NN + 7) / 8)
#define WSPLIT_ELEMS (LL * 4 * 128 * 16)   // [l][chunk][col][kpair]

// ---------------- device scratch ----------------
__device__ float g_h[(size_t)NN * DD];
__device__ float g_z[(size_t)NN * DD];
__device__ float g_as[NN];
__device__ float g_ad[NN];
__device__ int   g_cnt[NN];
__device__ int   g_off[NN + 1];
__device__ int   g_cur[NN];
__device__ int   g_csrc[ET];
__device__ int   g_scan[NN];
__device__ int   g_bsum[NBLK_SCAN];
__device__ int   g_boff[NBLK_SCAN];
__device__ float g_psumf[(size_t)NBLK_AGG * DD];
__device__ float g_psqf[(size_t)NBLK_AGG * DD];
__device__ float g_mu[DD];
__device__ float g_rsig[DD];
__device__ uint32_t g_wh[WSPLIT_ELEMS];
__device__ uint32_t g_wl[WSPLIT_ELEMS];

// ---------------- helpers ----------------
__device__ __forceinline__ uint32_t pack_bf2(float a, float b) {
    __nv_bfloat162 t = __floats2bfloat162_rn(a, b);
    return *(uint32_t*)&t;
}

__device__ __forceinline__ void mma16(float c[4], const uint32_t a[4], uint32_t b0, uint32_t b1) {
    asm volatile(
        "mma.sync.aligned.m16n8k16.row.col.f32.bf16.bf16.f32 "
        "{%0,%1,%2,%3},{%4,%5,%6,%7},{%8,%9},{%0,%1,%2,%3};"
        : "+f"(c[0]), "+f"(c[1]), "+f"(c[2]), "+f"(c[3])
        : "r"(a[0]), "r"(a[1]), "r"(a[2]), "r"(a[3]), "r"(b0), "r"(b1));
}

__device__ __forceinline__ void ldmx4(uint32_t d[4], const uint32_t* p) {
    uint32_t saddr = (uint32_t)__cvta_generic_to_shared(p);
    asm volatile("ldmatrix.sync.aligned.m8n8.x4.shared.b16 {%0,%1,%2,%3}, [%4];"
                 : "=r"(d[0]), "=r"(d[1]), "=r"(d[2]), "=r"(d[3]) : "r"(saddr));
}

__device__ __forceinline__ void cp_async16(const uint32_t* dst, const uint32_t* src) {
    uint32_t d = (uint32_t)__cvta_generic_to_shared(dst);
    asm volatile("cp.async.ca.shared.global [%0], [%1], 16;" :: "r"(d), "l"(src));
}

// ---------------- W bf16 hi/lo split precompute ----------------
__global__ void wsplit_kernel(const float* __restrict__ W) {
    int i = blockIdx.x * blockDim.x + threadIdx.x;
    if (i >= WSPLIT_ELEMS) return;
    int l = i / 8192;
    int rem = i - l * 8192;
    int c = rem >> 11;
    int rem2 = rem & 2047;
    int col = rem2 >> 4;
    int kp = rem2 & 15;
    int k = c * KC + 2 * kp;
    const float* Wl = W + (size_t)l * DD * DD;
    float w0 = Wl[(size_t)k * DD + col];
    float w1 = Wl[(size_t)(k + 1) * DD + col];
    uint32_t h = pack_bf2(w0, w1);
    float2 f = __bfloat1622float2(*(__nv_bfloat162*)&h);
    g_wh[i] = h;
    g_wl[i] = pack_bf2(w0 - f.x, w1 - f.y);
}

// ---------------- CSR build ----------------
__global__ void init_cnt_kernel() {
    int i = blockIdx.x * blockDim.x + threadIdx.x;
    if (i < NN) g_cnt[i] = 1;
}

__global__ void count_kernel(const int* __restrict__ ei) {
    int i = blockIdx.x * blockDim.x + threadIdx.x;
    if (i < EE) atomicAdd(&g_cnt[ei[EE + i]], 1);
}

__global__ void scan1_kernel() {
    __shared__ int sm[1024];
    int t = threadIdx.x;
    int i = blockIdx.x * 1024 + t;
    int v = (i < NN) ? g_cnt[i] : 0;
    sm[t] = v;
    __syncthreads();
#pragma unroll
    for (int o = 1; o < 1024; o <<= 1) {
        int tmp = (t >= o) ? sm[t - o] : 0;
        __syncthreads();
        sm[t] += tmp;
        __syncthreads();
    }
    if (i < NN) g_scan[i] = sm[t];
    if (t == 1023) g_bsum[blockIdx.x] = sm[t];
}

__global__ void scan2_kernel() {
    __shared__ int sm[64];
    int t = threadIdx.x;
    sm[t] = (t < NBLK_SCAN) ? g_bsum[t] : 0;
    __syncthreads();
#pragma unroll
    for (int o = 1; o < 64; o <<= 1) {
        int tmp = (t >= o) ? sm[t - o] : 0;
        __syncthreads();
        sm[t] += tmp;
        __syncthreads();
    }
    if (t < NBLK_SCAN) g_boff[t] = sm[t] - g_bsum[t];
}

__global__ void scan3_kernel() {
    int i = blockIdx.x * blockDim.x + threadIdx.x;
    if (i >= NN) return;
    int incl = g_scan[i] + g_boff[i >> 10];
    g_off[i + 1] = incl;
    g_cur[i] = incl - g_cnt[i];
    if (i == 0) g_off[0] = 0;
}

__global__ void fill_kernel(const int* __restrict__ ei) {
    int i = blockIdx.x * blockDim.x + threadIdx.x;
    if (i < EE) {
        int s = ei[i];
        int d = ei[EE + i];
        int p = atomicAdd(&g_cur[d], 1);
        g_csrc[p] = s;
    } else if (i < ET) {
        int v = i - EE;
        int p = atomicAdd(&g_cur[v], 1);
        g_csrc[p] = v;
    }
}

// ---------------- bf16 3-split GEMM, BM=64, cp.async B copy ----------------
__global__ void __launch_bounds__(256, 2) gemm_kernel(
    const float* __restrict__ zin, int layer,
    const float* __restrict__ asrc, const float* __restrict__ adst, int do_bn) {
    __shared__ __align__(16) uint32_t a_hi[BM][AST];
    __shared__ __align__(16) uint32_t a_lo[BM][AST];
    __shared__ __align__(16) uint32_t b_hi[128][AST];
    __shared__ __align__(16) uint32_t b_lo[128][AST];
    __shared__ float s_as[4][BM];
    __shared__ float s_ad[4][BM];

    int tid = threadIdx.x;
    int w = tid >> 5, lane = tid & 31;
    int wm = w & 1, wn = w >> 1;       // 2 row-groups x 4 col-groups (32x32 per warp)
    int block_row = blockIdx.x * BM;
    int qrow = lane >> 2, qcol = lane & 3;
    int lrow = lane & 7;
    int lsel = lane >> 3;

    const uint32_t* whL = g_wh + layer * 8192;
    const uint32_t* wlL = g_wl + layer * 8192;
    int bcol = tid >> 1;               // 0..127
    int bseg = (tid & 1) * 2;          // seg 0,1 or 2,3 (each seg = 4 words = 16B)

    float c[2][4][4];
#pragma unroll
    for (int m = 0; m < 2; m++)
#pragma unroll
        for (int n = 0; n < 4; n++)
#pragma unroll
            for (int i = 0; i < 4; i++) c[m][n][i] = 0.f;

    for (int cc = 0; cc < 4; ++cc) {
        int k0 = cc * KC;
        // ---- B chunk: cp.async straight copy of pre-split W (2x16B hi + 2x16B lo per thread)
        {
            const uint32_t* srcH = whL + cc * 2048 + bcol * 16 + bseg * 4;
            const uint32_t* srcL = wlL + cc * 2048 + bcol * 16 + bseg * 4;
            cp_async16(&b_hi[bcol][bseg * 4], srcH);
            cp_async16(&b_hi[bcol][bseg * 4 + 4], srcH + 4);
            cp_async16(&b_lo[bcol][bseg * 4], srcL);
            cp_async16(&b_lo[bcol][bseg * 4 + 4], srcL + 4);
            asm volatile("cp.async.commit_group;");
        }
        // ---- A chunk [64 x 32]: load fp32, optional BN+ReLU, hi/lo bf16 split ----
#pragma unroll
        for (int p = 0; p < 2; ++p) {
            int idx = p * 256 + tid;   // 0..511
            int r = idx >> 3;          // 0..63
            int c4 = (idx & 7) * 4;
            int gr = block_row + r;
            float4 v = make_float4(0.f, 0.f, 0.f, 0.f);
            if (gr < NN) v = *(const float4*)(zin + (size_t)gr * DD + k0 + c4);
            if (do_bn) {
                float4 mu = *(const float4*)(g_mu + k0 + c4);
                float4 rs = *(const float4*)(g_rsig + k0 + c4);
                v.x = fmaxf(0.f, (v.x - mu.x) * rs.x);
                v.y = fmaxf(0.f, (v.y - mu.y) * rs.y);
                v.z = fmaxf(0.f, (v.z - mu.z) * rs.z);
                v.w = fmaxf(0.f, (v.w - mu.w) * rs.w);
            }
            uint32_t h01 = pack_bf2(v.x, v.y);
            uint32_t h23 = pack_bf2(v.z, v.w);
            float2 f01 = __bfloat1622float2(*(__nv_bfloat162*)&h01);
            float2 f23 = __bfloat1622float2(*(__nv_bfloat162*)&h23);
            a_hi[r][c4 / 2] = h01;
            a_hi[r][c4 / 2 + 1] = h23;
            a_lo[r][c4 / 2] = pack_bf2(v.x - f01.x, v.y - f01.y);
            a_lo[r][c4 / 2 + 1] = pack_bf2(v.z - f23.x, v.w - f23.y);
        }
        asm volatile("cp.async.wait_group 0;");
        __syncthreads();
#pragma unroll
        for (int step = 0; step < 2; ++step) {
            int kq = step * 8;
            uint32_t ah[2][4], al[2][4];
#pragma unroll
            for (int m = 0; m < 2; ++m) {
                int r = wm * 32 + m * 16 + lrow + (lsel & 1) * 8;
                int kcol = kq + (lsel >> 1) * 4;
                ldmx4(ah[m], &a_hi[r][kcol]);
                ldmx4(al[m], &a_lo[r][kcol]);
            }
            uint32_t bh[2][4], bl[2][4];
#pragma unroll
            for (int np = 0; np < 2; ++np) {
                int col = wn * 32 + np * 16 + lrow + (lsel >> 1) * 8;
                int kcol = kq + (lsel & 1) * 4;
                ldmx4(bh[np], &b_hi[col][kcol]);
                ldmx4(bl[np], &b_lo[col][kcol]);
            }
#pragma unroll
            for (int np = 0; np < 2; ++np) {
#pragma unroll
                for (int sub = 0; sub < 2; ++sub) {
                    int n = np * 2 + sub;
                    uint32_t b0h = bh[np][sub * 2], b1h = bh[np][sub * 2 + 1];
                    uint32_t b0l = bl[np][sub * 2], b1l = bl[np][sub * 2 + 1];
                    mma16(c[0][n], ah[0], b0l, b1l);
                    mma16(c[0][n], al[0], b0h, b1h);
                    mma16(c[0][n], ah[0], b0h, b1h);
                    mma16(c[1][n], ah[1], b0l, b1l);
                    mma16(c[1][n], al[1], b0h, b1h);
                    mma16(c[1][n], ah[1], b0h, b1h);
                }
            }
        }
        __syncthreads();
    }

    // epilogue: store h (fp32) + fused attention dots
    float dsrc[2][2] = {{0.f, 0.f}, {0.f, 0.f}};
    float ddst[2][2] = {{0.f, 0.f}, {0.f, 0.f}};
#pragma unroll
    for (int n = 0; n < 4; ++n) {
        int col0 = wn * 32 + n * 8 + 2 * qcol;
        float as0 = asrc[col0], as1 = asrc[col0 + 1];
        float ad0 = adst[col0], ad1 = adst[col0 + 1];
#pragma unroll
        for (int m = 0; m < 2; ++m) {
            dsrc[m][0] += c[m][n][0] * as0 + c[m][n][1] * as1;
            dsrc[m][1] += c[m][n][2] * as0 + c[m][n][3] * as1;
            ddst[m][0] += c[m][n][0] * ad0 + c[m][n][1] * ad1;
            ddst[m][1] += c[m][n][2] * ad0 + c[m][n][3] * ad1;
            int row = block_row + wm * 32 + m * 16 + qrow;
            if (row < NN)
                *(float2*)(g_h + (size_t)row * DD + col0) = make_float2(c[m][n][0], c[m][n][1]);
            if (row + 8 < NN)
                *(float2*)(g_h + (size_t)(row + 8) * DD + col0) = make_float2(c[m][n][2], c[m][n][3]);
        }
    }
#pragma unroll
    for (int m = 0; m < 2; ++m)
#pragma unroll
        for (int hh = 0; hh < 2; ++hh) {
#pragma unroll
            for (int o = 1; o <= 2; o <<= 1) {
                dsrc[m][hh] += __shfl_xor_sync(0xffffffffu, dsrc[m][hh], o);
                ddst[m][hh] += __shfl_xor_sync(0xffffffffu, ddst[m][hh], o);
            }
        }
    if (qcol == 0) {
#pragma unroll
        for (int m = 0; m < 2; ++m) {
            int rl = wm * 32 + m * 16 + qrow;
            s_as[wn][rl] = dsrc[m][0];
            s_as[wn][rl + 8] = dsrc[m][1];
            s_ad[wn][rl] = ddst[m][0];
            s_ad[wn][rl + 8] = ddst[m][1];
        }
    }
    __syncthreads();
    if (tid < BM) {
        int gr = block_row + tid;
        if (gr < NN) {
            g_as[gr] = s_as[0][tid] + s_as[1][tid] + s_as[2][tid] + s_as[3][tid];
            g_ad[gr] = s_ad[0][tid] + s_ad[1][tid] + s_ad[2][tid] + s_ad[3][tid];
        }
    }
}

// ------- fused softmax + gather + BN partial stats: 8 warps = 8 nodes per block -------
__global__ void __launch_bounds__(256) aggregate_kernel(
    const float* __restrict__ bias, float* __restrict__ zout) {
    int n = (blockIdx.x * blockDim.x + threadIdx.x) >> 5;
    int w = threadIdx.x >> 5;
    int lane = threadIdx.x & 31;

    __shared__ float sredS[8][DD];
    __shared__ float sredQ[8][DD];

    float4 ov = make_float4(0.f, 0.f, 0.f, 0.f);
    if (n < NN) {
        int beg = g_off[n], end = g_off[n + 1];
        float adn = g_ad[n];
        float4 acc = make_float4(0.f, 0.f, 0.f, 0.f);
        float psum = 0.f;
        int j = beg;
        for (; j + 8 <= end; j += 8) {
            int s0 = __ldg(&g_csrc[j + 0]);
            int s1 = __ldg(&g_csrc[j + 1]);
            int s2 = __ldg(&g_csrc[j + 2]);
            int s3 = __ldg(&g_csrc[j + 3]);
            int s4 = __ldg(&g_csrc[j + 4]);
            int s5 = __ldg(&g_csrc[j + 5]);
            int s6 = __ldg(&g_csrc[j + 6]);
            int s7 = __ldg(&g_csrc[j + 7]);
            float e0 = __ldg(&g_as[s0]) + adn;
            float e1 = __ldg(&g_as[s1]) + adn;
            float e2 = __ldg(&g_as[s2]) + adn;
            float e3 = __ldg(&g_as[s3]) + adn;
            float e4 = __ldg(&g_as[s4]) + adn;
            float e5 = __ldg(&g_as[s5]) + adn;
            float e6 = __ldg(&g_as[s6]) + adn;
            float e7 = __ldg(&g_as[s7]) + adn;
            e0 = (e0 > 0.f) ? e0 : SLOPE * e0;
            e1 = (e1 > 0.f) ? e1 : SLOPE * e1;
            e2 = (e2 > 0.f) ? e2 : SLOPE * e2;
            e3 = (e3 > 0.f) ? e3 : SLOPE * e3;
            e4 = (e4 > 0.f) ? e4 : SLOPE * e4;
            e5 = (e5 > 0.f) ? e5 : SLOPE * e5;
            e6 = (e6 > 0.f) ? e6 : SLOPE * e6;
            e7 = (e7 > 0.f) ? e7 : SLOPE * e7;
            float p0 = __expf(e0), p1 = __expf(e1), p2 = __expf(e2), p3 = __expf(e3);
            float p4 = __expf(e4), p5 = __expf(e5), p6 = __expf(e6), p7 = __expf(e7);
            float4 h0 = __ldg((const float4*)(g_h + (size_t)s0 * DD + lane * 4));
            float4 h1 = __ldg((const float4*)(g_h + (size_t)s1 * DD + lane * 4));
            float4 h2 = __ldg((const float4*)(g_h + (size_t)s2 * DD + lane * 4));
            float4 h3 = __ldg((const float4*)(g_h + (size_t)s3 * DD + lane * 4));
            float4 h4 = __ldg((const float4*)(g_h + (size_t)s4 * DD + lane * 4));
            float4 h5 = __ldg((const float4*)(g_h + (size_t)s5 * DD + lane * 4));
            float4 h6 = __ldg((const float4*)(g_h + (size_t)s6 * DD + lane * 4));
            float4 h7 = __ldg((const float4*)(g_h + (size_t)s7 * DD + lane * 4));
            acc.x += p0 * h0.x + p1 * h1.x + p2 * h2.x + p3 * h3.x
                   + p4 * h4.x + p5 * h5.x + p6 * h6.x + p7 * h7.x;
            acc.y += p0 * h0.y + p1 * h1.y + p2 * h2.y + p3 * h3.y
                   + p4 * h4.y + p5 * h5.y + p6 * h6.y + p7 * h7.y;
            acc.z += p0 * h0.z + p1 * h1.z + p2 * h2.z + p3 * h3.z
                   + p4 * h4.z + p5 * h5.z + p6 * h6.z + p7 * h7.z;
            acc.w += p0 * h0.w + p1 * h1.w + p2 * h2.w + p3 * h3.w
                   + p4 * h4.w + p5 * h5.w + p6 * h6.w + p7 * h7.w;
            psum += p0 + p1 + p2 + p3 + p4 + p5 + p6 + p7;
        }
        for (; j < end; ++j) {
            int s0 = __ldg(&g_csrc[j]);
            float e0 = __ldg(&g_as[s0]) + adn;
            e0 = (e0 > 0.f) ? e0 : SLOPE * e0;
            float p0 = __expf(e0);
            float4 h0 = __ldg((const float4*)(g_h + (size_t)s0 * DD + lane * 4));
            acc.x += p0 * h0.x;
            acc.y += p0 * h0.y;
            acc.z += p0 * h0.z;
            acc.w += p0 * h0.w;
            psum += p0;
        }
        float rinv = 1.f / psum;
        float4 bv = *(const float4*)(bias + lane * 4);
        ov = make_float4(acc.x * rinv + bv.x, acc.y * rinv + bv.y,
                         acc.z * rinv + bv.z, acc.w * rinv + bv.w);
        *(float4*)(zout + (size_t)n * DD + lane * 4) = ov;
    }
    *(float4*)&sredS[w][lane * 4] = ov;
    *(float4*)&sredQ[w][lane * 4] =
        make_float4(ov.x * ov.x, ov.y * ov.y, ov.z * ov.z, ov.w * ov.w);
    __syncthreads();
    int t = threadIdx.x;
    if (t < DD) {
        float s = 0.f, q = 0.f;
#pragma unroll
        for (int ww = 0; ww < 8; ++ww) {
            s += sredS[ww][t];
            q += sredQ[ww][t];
        }
        g_psumf[(size_t)blockIdx.x * DD + t] = s;
        g_psqf[(size_t)blockIdx.x * DD + t] = q;
    }
}

// ---------------- BN stats final reduce ----------------
__global__ void reduce_stats_kernel() {
    int d = blockIdx.x;
    int t = threadIdx.x;
    double s = 0.0, q = 0.0;
    for (int b = t; b < NBLK_AGG; b += 256) {
        s += (double)g_psumf[(size_t)b * DD + d];
        q += (double)g_psqf[(size_t)b * DD + d];
    }
    __shared__ double shs[256], shq[256];
    shs[t] = s;
    shq[t] = q;
    __syncthreads();
#pragma unroll
    for (int o = 128; o > 0; o >>= 1) {
        if (t < o) {
            shs[t] += shs[t + o];
            shq[t] += shq[t + o];
        }
        __syncthreads();
    }
    if (t == 0) {
        double mu = shs[0] / (double)NN;
        double var = shq[0] / (double)NN - mu * mu;
        g_mu[d] = (float)mu;
        g_rsig[d] = (float)(1.0 / sqrt(var + 1e-5));
    }
}

__global__ void bn_apply_kernel(const float* __restrict__ zin, float* __restrict__ zo) {
    int i = blockIdx.x * blockDim.x + threadIdx.x;
    if (i >= NN * DD) return;
    int d = i & 127;
    float v = (zin[i] - g_mu[d]) * g_rsig[d];
    zo[i] = (v > 0.f) ? v : 0.f;
}

// ---------------- launch ----------------
extern "C" void kernel_launch(void* const* d_in, const int* in_sizes, int n_in,
                              void* d_out, int out_size) {
    const float* x = (const float*)d_in[0];
    const int* ei = (const int*)d_in[1];
    const float* W = (const float*)d_in[2];
    const float* a_src = (const float*)d_in[3];
    const float* a_dst = (const float*)d_in[4];
    const float* b = (const float*)d_in[5];
    float* out = (float*)d_out;

    float* zptr = nullptr;
    cudaGetSymbolAddress((void**)&zptr, g_z);

    static cudaStream_t s2 = nullptr;
    static cudaEvent_t ev_fork = nullptr, ev_join = nullptr;
    if (!s2) {
        cudaStreamCreateWithFlags(&s2, cudaStreamNonBlocking);
        cudaEventCreateWithFlags(&ev_fork, cudaEventDisableTiming);
        cudaEventCreateWithFlags(&ev_join, cudaEventDisableTiming);
    }

    cudaEventRecord(ev_fork, 0);
    cudaStreamWaitEvent(s2, ev_fork, 0);

    wsplit_kernel<<<(WSPLIT_ELEMS + 255) / 256, 256, 0, s2>>>(W);
    init_cnt_kernel<<<(NN + 255) / 256, 256>>>();
    count_kernel<<<(EE + 255) / 256, 256>>>(ei);
    scan1_kernel<<<NBLK_SCAN, 1024>>>();
    gemm_kernel<<<NBLK_GEMM, 256, 0, s2>>>(x, 0, a_src, a_dst, 0);
    scan2_kernel<<<1, 64>>>();
    scan3_kernel<<<(NN + 255) / 256, 256>>>();
    fill_kernel<<<(ET + 255) / 256, 256>>>(ei);

    cudaEventRecord(ev_join, s2);
    cudaStreamWaitEvent(0, ev_join, 0);

    for (int l = 0; l < LL; ++l) {
        if (l > 0)
            gemm_kernel<<<NBLK_GEMM, 256>>>(zptr, l, a_src + l * DD, a_dst + l * DD, 1);
        aggregate_kernel<<<NBLK_AGG, 256>>>(b + l * DD, zptr);
        reduce_stats_kernel<<<DD, 256>>>();
    }
    bn_apply_kernel<<<(NN * DD + 255) / 256, 256>>>(zptr, out);
}

// round 13
// speedup vs baseline: 1.0303x; 1.0303x over previous
#include <cuda_runtime.h>
#include <cuda_bf16.h>
#include <cstdint>

#define NN 50000
#define DD 128
#define EE 1600000
#define ET (EE + NN)
#define LL 3
#define SLOPE 0.2f
#define NBLK_SCAN ((NN + 1023) / 1024)
#define KC 32
#define AST 20
#define NBLK_AGG ((NN + 7) / 8)
#define WSPLIT_ELEMS (LL * 4 * 128 * 16)   // [l][chunk][col][kpair]
#define BUFW (128 * AST)                   // 2560 words per buffer per array
#define SMEM_WORDS_G (4 * 2 * BUFW + 512)
#define SMEM_BYTES_G (SMEM_WORDS_G * 4)    // 83968 B

// ---------------- device scratch ----------------
__device__ float g_h[(size_t)NN * DD];
__device__ float g_z[(size_t)NN * DD];
__device__ float g_as[NN];
__device__ float g_ad[NN];
__device__ int   g_cnt[NN];
__device__ int   g_off[NN + 1];
__device__ int   g_cur[NN];
__device__ int   g_csrc[ET];
__device__ int   g_scan[NN];
__device__ int   g_bsum[NBLK_SCAN];
__device__ int   g_boff[NBLK_SCAN];
__device__ float g_psumf[(size_t)NBLK_AGG * DD];
__device__ float g_psqf[(size_t)NBLK_AGG * DD];
__device__ float g_mu[DD];
__device__ float g_rsig[DD];
__device__ uint32_t g_wh[WSPLIT_ELEMS];
__device__ uint32_t g_wl[WSPLIT_ELEMS];

// ---------------- helpers ----------------
__device__ __forceinline__ uint32_t pack_bf2(float a, float b) {
    __nv_bfloat162 t = __floats2bfloat162_rn(a, b);
    return *(uint32_t*)&t;
}

__device__ __forceinline__ void mma16(float c[4], const uint32_t a[4], uint32_t b0, uint32_t b1) {
    asm volatile(
        "mma.sync.aligned.m16n8k16.row.col.f32.bf16.bf16.f32 "
        "{%0,%1,%2,%3},{%4,%5,%6,%7},{%8,%9},{%0,%1,%2,%3};"
        : "+f"(c[0]), "+f"(c[1]), "+f"(c[2]), "+f"(c[3])
        : "r"(a[0]), "r"(a[1]), "r"(a[2]), "r"(a[3]), "r"(b0), "r"(b1));
}

__device__ __forceinline__ void ldmx4(uint32_t d[4], const uint32_t* p) {
    uint32_t saddr = (uint32_t)__cvta_generic_to_shared(p);
    asm volatile("ldmatrix.sync.aligned.m8n8.x4.shared.b16 {%0,%1,%2,%3}, [%4];"
                 : "=r"(d[0]), "=r"(d[1]), "=r"(d[2]), "=r"(d[3]) : "r"(saddr));
}

__device__ __forceinline__ void cp_async16(const uint32_t* dst, const uint32_t* src) {
    uint32_t d = (uint32_t)__cvta_generic_to_shared(dst);
    asm volatile("cp.async.ca.shared.global [%0], [%1], 16;" :: "r"(d), "l"(src));
}

// ---------------- W bf16 hi/lo split precompute ----------------
__global__ void wsplit_kernel(const float* __restrict__ W) {
    int i = blockIdx.x * blockDim.x + threadIdx.x;
    if (i >= WSPLIT_ELEMS) return;
    int l = i / 8192;
    int rem = i - l * 8192;
    int c = rem >> 11;
    int rem2 = rem & 2047;
    int col = rem2 >> 4;
    int kp = rem2 & 15;
    int k = c * KC + 2 * kp;
    const float* Wl = W + (size_t)l * DD * DD;
    float w0 = Wl[(size_t)k * DD + col];
    float w1 = Wl[(size_t)(k + 1) * DD + col];
    uint32_t h = pack_bf2(w0, w1);
    float2 f = __bfloat1622float2(*(__nv_bfloat162*)&h);
    g_wh[i] = h;
    g_wl[i] = pack_bf2(w0 - f.x, w1 - f.y);
}

// ---------------- CSR build ----------------
__global__ void init_cnt_kernel() {
    int i = blockIdx.x * blockDim.x + threadIdx.x;
    if (i < NN) g_cnt[i] = 1;
}

__global__ void count_kernel(const int* __restrict__ ei) {
    int i = blockIdx.x * blockDim.x + threadIdx.x;
    if (i < EE) atomicAdd(&g_cnt[ei[EE + i]], 1);
}

__global__ void scan1_kernel() {
    __shared__ int sm[1024];
    int t = threadIdx.x;
    int i = blockIdx.x * 1024 + t;
    int v = (i < NN) ? g_cnt[i] : 0;
    sm[t] = v;
    __syncthreads();
#pragma unroll
    for (int o = 1; o < 1024; o <<= 1) {
        int tmp = (t >= o) ? sm[t - o] : 0;
        __syncthreads();
        sm[t] += tmp;
        __syncthreads();
    }
    if (i < NN) g_scan[i] = sm[t];
    if (t == 1023) g_bsum[blockIdx.x] = sm[t];
}

__global__ void scan2_kernel() {
    __shared__ int sm[64];
    int t = threadIdx.x;
    sm[t] = (t < NBLK_SCAN) ? g_bsum[t] : 0;
    __syncthreads();
#pragma unroll
    for (int o = 1; o < 64; o <<= 1) {
        int tmp = (t >= o) ? sm[t - o] : 0;
        __syncthreads();
        sm[t] += tmp;
        __syncthreads();
    }
    if (t < NBLK_SCAN) g_boff[t] = sm[t] - g_bsum[t];
}

__global__ void scan3_kernel() {
    int i = blockIdx.x * blockDim.x + threadIdx.x;
    if (i >= NN) return;
    int incl = g_scan[i] + g_boff[i >> 10];
    g_off[i + 1] = incl;
    g_cur[i] = incl - g_cnt[i];
    if (i == 0) g_off[0] = 0;
}

__global__ void fill_kernel(const int* __restrict__ ei) {
    int i = blockIdx.x * blockDim.x + threadIdx.x;
    if (i < EE) {
        int s = ei[i];
        int d = ei[EE + i];
        int p = atomicAdd(&g_cur[d], 1);
        g_csrc[p] = s;
    } else if (i < ET) {
        int v = i - EE;
        int p = atomicAdd(&g_cur[v], 1);
        g_csrc[p] = v;
    }
}

// ---------------- GEMM piece helpers ----------------
__device__ __forceinline__ void load_rawA(const float* __restrict__ zin,
                                          int block_row, int tid, int k0, float4 pa[4]) {
#pragma unroll
    for (int p = 0; p < 4; ++p) {
        int idx = p * 256 + tid;
        int r = idx >> 3;
        int c4 = (idx & 7) * 4;
        int gr = block_row + r;
        pa[p] = make_float4(0.f, 0.f, 0.f, 0.f);
        if (gr < NN) pa[p] = *(const float4*)(zin + (size_t)gr * DD + k0 + c4);
    }
}

__device__ __forceinline__ void storeA(uint32_t* aH, uint32_t* aL,
                                       int tid, int k0, int do_bn, const float4 pa[4]) {
#pragma unroll
    for (int p = 0; p < 4; ++p) {
        int idx = p * 256 + tid;
        int r = idx >> 3;
        int c4 = (idx & 7) * 4;
        float4 v = pa[p];
        if (do_bn) {
            float4 mu = *(const float4*)(g_mu + k0 + c4);
            float4 rs = *(const float4*)(g_rsig + k0 + c4);
            v.x = fmaxf(0.f, (v.x - mu.x) * rs.x);
            v.y = fmaxf(0.f, (v.y - mu.y) * rs.y);
            v.z = fmaxf(0.f, (v.z - mu.z) * rs.z);
            v.w = fmaxf(0.f, (v.w - mu.w) * rs.w);
        }
        uint32_t h01 = pack_bf2(v.x, v.y);
        uint32_t h23 = pack_bf2(v.z, v.w);
        float2 f01 = __bfloat1622float2(*(__nv_bfloat162*)&h01);
        float2 f23 = __bfloat1622float2(*(__nv_bfloat162*)&h23);
        uint2 hh = make_uint2(h01, h23);
        uint2 ll = make_uint2(pack_bf2(v.x - f01.x, v.y - f01.y),
                              pack_bf2(v.z - f23.x, v.w - f23.y));
        *(uint2*)&aH[r * AST + c4 / 2] = hh;   // 8B-aligned (AST=20, c4/2 even)
        *(uint2*)&aL[r * AST + c4 / 2] = ll;
    }
}

// ---------------- bf16 3-split GEMM, BM=128, double-buffered + cp.async B ----------------
__global__ void __launch_bounds__(256, 2) gemm_kernel(
    const float* __restrict__ zin, int layer,
    const float* __restrict__ asrc, const float* __restrict__ adst, int do_bn) {
    extern __shared__ __align__(16) uint32_t dsm[];
    uint32_t* aH = dsm;                  // [2][128][AST]
    uint32_t* aL = aH + 2 * BUFW;
    uint32_t* bH = aL + 2 * BUFW;
    uint32_t* bL = bH + 2 * BUFW;
    float* sAS = (float*)(bL + 2 * BUFW);  // [2][128]
    float* sAD = sAS + 256;

    int tid = threadIdx.x;
    int w = tid >> 5, lane = tid & 31;
    int wm = w & 3, wn = w >> 2;
    int block_row = blockIdx.x * 128;
    int qrow = lane >> 2, qcol = lane & 3;
    int lrow = lane & 7;
    int lsel = lane >> 3;

    const uint32_t* whL = g_wh + layer * 8192;
    const uint32_t* wlL = g_wl + layer * 8192;
    int bcol = tid >> 1;
    int bseg = (tid & 1) * 2;

    float c[2][8][4];
#pragma unroll
    for (int m = 0; m < 2; m++)
#pragma unroll
        for (int n = 0; n < 8; n++)
#pragma unroll
            for (int i = 0; i < 4; i++) c[m][n][i] = 0.f;

    float4 pa[4];

    // prologue: chunk 0
    {
        const uint32_t* srcH = whL + bcol * 16 + bseg * 4;
        const uint32_t* srcL = wlL + bcol * 16 + bseg * 4;
        cp_async16(&bH[bcol * AST + bseg * 4], srcH);
        cp_async16(&bH[bcol * AST + bseg * 4 + 4], srcH + 4);
        cp_async16(&bL[bcol * AST + bseg * 4], srcL);
        cp_async16(&bL[bcol * AST + bseg * 4 + 4], srcL + 4);
        asm volatile("cp.async.commit_group;");
        load_rawA(zin, block_row, tid, 0, pa);
        storeA(aH, aL, tid, 0, do_bn, pa);
        asm volatile("cp.async.wait_group 0;");
        __syncthreads();
    }

#pragma unroll
    for (int cc = 0; cc < 4; ++cc) {
        int cur = cc & 1;
        int nxt = cur ^ 1;
        if (cc < 3) {
            const uint32_t* srcH = whL + (cc + 1) * 2048 + bcol * 16 + bseg * 4;
            const uint32_t* srcL = wlL + (cc + 1) * 2048 + bcol * 16 + bseg * 4;
            cp_async16(&bH[nxt * BUFW + bcol * AST + bseg * 4], srcH);
            cp_async16(&bH[nxt * BUFW + bcol * AST + bseg * 4 + 4], srcH + 4);
            cp_async16(&bL[nxt * BUFW + bcol * AST + bseg * 4], srcL);
            cp_async16(&bL[nxt * BUFW + bcol * AST + bseg * 4 + 4], srcL + 4);
            asm volatile("cp.async.commit_group;");
            load_rawA(zin, block_row, tid, (cc + 1) * KC, pa);
        }

        const uint32_t* aHc = aH + cur * BUFW;
        const uint32_t* aLc = aL + cur * BUFW;
        const uint32_t* bHc = bH + cur * BUFW;
        const uint32_t* bLc = bL + cur * BUFW;
#pragma unroll
        for (int step = 0; step < 2; ++step) {
            int kq = step * 8;
            uint32_t ah[2][4], al_[2][4];
#pragma unroll
            for (int m = 0; m < 2; ++m) {
                int r = wm * 32 + m * 16 + lrow + (lsel & 1) * 8;
                int kcol = kq + (lsel >> 1) * 4;
                ldmx4(ah[m], &aHc[r * AST + kcol]);
                ldmx4(al_[m], &aLc[r * AST + kcol]);
            }
            uint32_t bh[4][4], bl_[4][4];
#pragma unroll
            for (int np = 0; np < 4; ++np) {
                int col = wn * 64 + np * 16 + lrow + (lsel >> 1) * 8;
                int kcol = kq + (lsel & 1) * 4;
                ldmx4(bh[np], &bHc[col * AST + kcol]);
                ldmx4(bl_[np], &bLc[col * AST + kcol]);
            }
#pragma unroll
            for (int np = 0; np < 4; ++np) {
#pragma unroll
                for (int sub = 0; sub < 2; ++sub) {
                    int n = np * 2 + sub;
                    uint32_t b0h = bh[np][sub * 2], b1h = bh[np][sub * 2 + 1];
                    uint32_t b0l = bl_[np][sub * 2], b1l = bl_[np][sub * 2 + 1];
                    mma16(c[0][n], ah[0], b0l, b1l);
                    mma16(c[0][n], al_[0], b0h, b1h);
                    mma16(c[0][n], ah[0], b0h, b1h);
                    mma16(c[1][n], ah[1], b0l, b1l);
                    mma16(c[1][n], al_[1], b0h, b1h);
                    mma16(c[1][n], ah[1], b0h, b1h);
                }
            }
        }
        if (cc < 3) {
            storeA(aH + nxt * BUFW, aL + nxt * BUFW, tid, (cc + 1) * KC, do_bn, pa);
            asm volatile("cp.async.wait_group 0;");
        }
        __syncthreads();
    }

    // epilogue: store h (fp32) + fused attention dots
    float dsrc[2][2] = {{0.f, 0.f}, {0.f, 0.f}};
    float ddst[2][2] = {{0.f, 0.f}, {0.f, 0.f}};
#pragma unroll
    for (int n = 0; n < 8; ++n) {
        int col0 = wn * 64 + n * 8 + 2 * qcol;
        float as0 = asrc[col0], as1 = asrc[col0 + 1];
        float ad0 = adst[col0], ad1 = adst[col0 + 1];
#pragma unroll
        for (int m = 0; m < 2; ++m) {
            dsrc[m][0] += c[m][n][0] * as0 + c[m][n][1] * as1;
            dsrc[m][1] += c[m][n][2] * as0 + c[m][n][3] * as1;
            ddst[m][0] += c[m][n][0] * ad0 + c[m][n][1] * ad1;
            ddst[m][1] += c[m][n][2] * ad0 + c[m][n][3] * ad1;
            int row = block_row + wm * 32 + m * 16 + qrow;
            if (row < NN)
                *(float2*)(g_h + (size_t)row * DD + col0) = make_float2(c[m][n][0], c[m][n][1]);
            if (row + 8 < NN)
                *(float2*)(g_h + (size_t)(row + 8) * DD + col0) = make_float2(c[m][n][2], c[m][n][3]);
        }
    }
#pragma unroll
    for (int m = 0; m < 2; ++m)
#pragma unroll
        for (int hh = 0; hh < 2; ++hh) {
#pragma unroll
            for (int o = 1; o <= 2; o <<= 1) {
                dsrc[m][hh] += __shfl_xor_sync(0xffffffffu, dsrc[m][hh], o);
                ddst[m][hh] += __shfl_xor_sync(0xffffffffu, ddst[m][hh], o);
            }
        }
    if (qcol == 0) {
#pragma unroll
        for (int m = 0; m < 2; ++m) {
            int rl = wm * 32 + m * 16 + qrow;
            sAS[wn * 128 + rl] = dsrc[m][0];
            sAS[wn * 128 + rl + 8] = dsrc[m][1];
            sAD[wn * 128 + rl] = ddst[m][0];
            sAD[wn * 128 + rl + 8] = ddst[m][1];
        }
    }
    __syncthreads();
    if (tid < 128) {
        int gr = block_row + tid;
        if (gr < NN) {
            g_as[gr] = sAS[tid] + sAS[128 + tid];
            g_ad[gr] = sAD[tid] + sAD[128 + tid];
        }
    }
}

// ------- fused softmax + gather + BN partial stats: 8 warps = 8 nodes per block -------
__global__ void __launch_bounds__(256) aggregate_kernel(
    const float* __restrict__ bias, float* __restrict__ zout) {
    int n = (blockIdx.x * blockDim.x + threadIdx.x) >> 5;
    int w = threadIdx.x >> 5;
    int lane = threadIdx.x & 31;

    __shared__ float sredS[8][DD];
    __shared__ float sredQ[8][DD];

    float4 ov = make_float4(0.f, 0.f, 0.f, 0.f);
    if (n < NN) {
        int beg = g_off[n], end = g_off[n + 1];
        float adn = g_ad[n];
        float4 acc = make_float4(0.f, 0.f, 0.f, 0.f);
        float psum = 0.f;
        int j = beg;
        for (; j + 8 <= end; j += 8) {
            int s0 = __ldg(&g_csrc[j + 0]);
            int s1 = __ldg(&g_csrc[j + 1]);
            int s2 = __ldg(&g_csrc[j + 2]);
            int s3 = __ldg(&g_csrc[j + 3]);
            int s4 = __ldg(&g_csrc[j + 4]);
            int s5 = __ldg(&g_csrc[j + 5]);
            int s6 = __ldg(&g_csrc[j + 6]);
            int s7 = __ldg(&g_csrc[j + 7]);
            float e0 = __ldg(&g_as[s0]) + adn;
            float e1 = __ldg(&g_as[s1]) + adn;
            float e2 = __ldg(&g_as[s2]) + adn;
            float e3 = __ldg(&g_as[s3]) + adn;
            float e4 = __ldg(&g_as[s4]) + adn;
            float e5 = __ldg(&g_as[s5]) + adn;
            float e6 = __ldg(&g_as[s6]) + adn;
            float e7 = __ldg(&g_as[s7]) + adn;
            e0 = (e0 > 0.f) ? e0 : SLOPE * e0;
            e1 = (e1 > 0.f) ? e1 : SLOPE * e1;
            e2 = (e2 > 0.f) ? e2 : SLOPE * e2;
            e3 = (e3 > 0.f) ? e3 : SLOPE * e3;
            e4 = (e4 > 0.f) ? e4 : SLOPE * e4;
            e5 = (e5 > 0.f) ? e5 : SLOPE * e5;
            e6 = (e6 > 0.f) ? e6 : SLOPE * e6;
            e7 = (e7 > 0.f) ? e7 : SLOPE * e7;
            float p0 = __expf(e0), p1 = __expf(e1), p2 = __expf(e2), p3 = __expf(e3);
            float p4 = __expf(e4), p5 = __expf(e5), p6 = __expf(e6), p7 = __expf(e7);
            float4 h0 = __ldg((const float4*)(g_h + (size_t)s0 * DD + lane * 4));
            float4 h1 = __ldg((const float4*)(g_h + (size_t)s1 * DD + lane * 4));
            float4 h2 = __ldg((const float4*)(g_h + (size_t)s2 * DD + lane * 4));
            float4 h3 = __ldg((const float4*)(g_h + (size_t)s3 * DD + lane * 4));
            float4 h4 = __ldg((const float4*)(g_h + (size_t)s4 * DD + lane * 4));
            float4 h5 = __ldg((const float4*)(g_h + (size_t)s5 * DD + lane * 4));
            float4 h6 = __ldg((const float4*)(g_h + (size_t)s6 * DD + lane * 4));
            float4 h7 = __ldg((const float4*)(g_h + (size_t)s7 * DD + lane * 4));
            acc.x += p0 * h0.x + p1 * h1.x + p2 * h2.x + p3 * h3.x
                   + p4 * h4.x + p5 * h5.x + p6 * h6.x + p7 * h7.x;
            acc.y += p0 * h0.y + p1 * h1.y + p2 * h2.y + p3 * h3.y
                   + p4 * h4.y + p5 * h5.y + p6 * h6.y + p7 * h7.y;
            acc.z += p0 * h0.z + p1 * h1.z + p2 * h2.z + p3 * h3.z
                   + p4 * h4.z + p5 * h5.z + p6 * h6.z + p7 * h7.z;
            acc.w += p0 * h0.w + p1 * h1.w + p2 * h2.w + p3 * h3.w
                   + p4 * h4.w + p5 * h5.w + p6 * h6.w + p7 * h7.w;
            psum += p0 + p1 + p2 + p3 + p4 + p5 + p6 + p7;
        }
        for (; j < end; ++j) {
            int s0 = __ldg(&g_csrc[j]);
            float e0 = __ldg(&g_as[s0]) + adn;
            e0 = (e0 > 0.f) ? e0 : SLOPE * e0;
            float p0 = __expf(e0);
            float4 h0 = __ldg((const float4*)(g_h + (size_t)s0 * DD + lane * 4));
            acc.x += p0 * h0.x;
            acc.y += p0 * h0.y;
            acc.z += p0 * h0.z;
            acc.w += p0 * h0.w;
            psum += p0;
        }
        float rinv = 1.f / psum;
        float4 bv = *(const float4*)(bias + lane * 4);
        ov = make_float4(acc.x * rinv + bv.x, acc.y * rinv + bv.y,
                         acc.z * rinv + bv.z, acc.w * rinv + bv.w);
        *(float4*)(zout + (size_t)n * DD + lane * 4) = ov;
    }
    *(float4*)&sredS[w][lane * 4] = ov;
    *(float4*)&sredQ[w][lane * 4] =
        make_float4(ov.x * ov.x, ov.y * ov.y, ov.z * ov.z, ov.w * ov.w);
    __syncthreads();
    int t = threadIdx.x;
    if (t < DD) {
        float s = 0.f, q = 0.f;
#pragma unroll
        for (int ww = 0; ww < 8; ++ww) {
            s += sredS[ww][t];
            q += sredQ[ww][t];
        }
        g_psumf[(size_t)blockIdx.x * DD + t] = s;
        g_psqf[(size_t)blockIdx.x * DD + t] = q;
    }
}

// ---------------- BN stats final reduce ----------------
__global__ void reduce_stats_kernel() {
    int d = blockIdx.x;
    int t = threadIdx.x;
    double s = 0.0, q = 0.0;
    for (int b = t; b < NBLK_AGG; b += 256) {
        s += (double)g_psumf[(size_t)b * DD + d];
        q += (double)g_psqf[(size_t)b * DD + d];
    }
    __shared__ double shs[256], shq[256];
    shs[t] = s;
    shq[t] = q;
    __syncthreads();
#pragma unroll
    for (int o = 128; o > 0; o >>= 1) {
        if (t < o) {
            shs[t] += shs[t + o];
            shq[t] += shq[t + o];
        }
        __syncthreads();
    }
    if (t == 0) {
        double mu = shs[0] / (double)NN;
        double var = shq[0] / (double)NN - mu * mu;
        g_mu[d] = (float)mu;
        g_rsig[d] = (float)(1.0 / sqrt(var + 1e-5));
    }
}

__global__ void bn_apply_kernel(const float* __restrict__ zin, float* __restrict__ zo) {
    int i = blockIdx.x * blockDim.x + threadIdx.x;
    if (i >= NN * DD) return;
    int d = i & 127;
    float v = (zin[i] - g_mu[d]) * g_rsig[d];
    zo[i] = (v > 0.f) ? v : 0.f;
}

// ---------------- launch ----------------
extern "C" void kernel_launch(void* const* d_in, const int* in_sizes, int n_in,
                              void* d_out, int out_size) {
    const float* x = (const float*)d_in[0];
    const int* ei = (const int*)d_in[1];
    const float* W = (const float*)d_in[2];
    const float* a_src = (const float*)d_in[3];
    const float* a_dst = (const float*)d_in[4];
    const float* b = (const float*)d_in[5];
    float* out = (float*)d_out;

    float* zptr = nullptr;
    cudaGetSymbolAddress((void**)&zptr, g_z);

    static cudaStream_t s2 = nullptr;
    static cudaEvent_t ev_fork = nullptr, ev_join = nullptr;
    if (!s2) {
        cudaStreamCreateWithFlags(&s2, cudaStreamNonBlocking);
        cudaEventCreateWithFlags(&ev_fork, cudaEventDisableTiming);
        cudaEventCreateWithFlags(&ev_join, cudaEventDisableTiming);
        cudaFuncSetAttribute(gemm_kernel, cudaFuncAttributeMaxDynamicSharedMemorySize,
                             SMEM_BYTES_G);
    }

    cudaEventRecord(ev_fork, 0);
    cudaStreamWaitEvent(s2, ev_fork, 0);

    wsplit_kernel<<<(WSPLIT_ELEMS + 255) / 256, 256, 0, s2>>>(W);
    init_cnt_kernel<<<(NN + 255) / 256, 256>>>();
    count_kernel<<<(EE + 255) / 256, 256>>>(ei);
    scan1_kernel<<<NBLK_SCAN, 1024>>>();
    gemm_kernel<<<(NN + 127) / 128, 256, SMEM_BYTES_G, s2>>>(x, 0, a_src, a_dst, 0);
    scan2_kernel<<<1, 64>>>();
    scan3_kernel<<<(NN + 255) / 256, 256>>>();
    fill_kernel<<<(ET + 255) / 256, 256>>>(ei);

    cudaEventRecord(ev_join, s2);
    cudaStreamWaitEvent(0, ev_join, 0);

    for (int l = 0; l < LL; ++l) {
        if (l > 0)
            gemm_kernel<<<(NN + 127) / 128, 256, SMEM_BYTES_G>>>(
                zptr, l, a_src + l * DD, a_dst + l * DD, 1);
        aggregate_kernel<<<NBLK_AGG, 256>>>(b + l * DD, zptr);
        reduce_stats_kernel<<<DD, 256>>>();
    }
    bn_apply_kernel<<<(NN * DD + 255) / 256, 256>>>(zptr, out);
}

// round 14
// speedup vs baseline: 1.0948x; 1.0625x over previous
#include <cuda_runtime.h>
#include <cuda_bf16.h>
#include <cuda_fp16.h>
#include <cstdint>

#define NN 50000
#define DD 128
#define EE 1600000
#define ET (EE + NN)
#define LL 3
#define SLOPE 0.2f
#define NBLK_SCAN ((NN + 1023) / 1024)
#define KC 32
#define AST 20
#define NBLK_AGG ((NN + 7) / 8)
#define WSPLIT_ELEMS (LL * 4 * 128 * 16)
#define BUFW (128 * AST)
#define SMEM_WORDS_G (4 * 2 * BUFW + 512)
#define SMEM_BYTES_G (SMEM_WORDS_G * 4)

// ---------------- device scratch ----------------
__device__ __half g_hf[(size_t)NN * DD];   // h in fp16 (gather operand; eps 2^-11)
__device__ float g_z[(size_t)NN * DD];
__device__ float g_as[NN];
__device__ float g_ad[NN];
__device__ int   g_cnt[NN];
__device__ int   g_off[NN + 1];
__device__ int   g_cur[NN];
__device__ int   g_csrc[ET];
__device__ int   g_scan[NN];
__device__ int   g_bsum[NBLK_SCAN];
__device__ int   g_boff[NBLK_SCAN];
__device__ float g_psumf[(size_t)NBLK_AGG * DD];
__device__ float g_psqf[(size_t)NBLK_AGG * DD];
__device__ float g_mu[DD];
__device__ float g_rsig[DD];
__device__ uint32_t g_wh[WSPLIT_ELEMS];
__device__ uint32_t g_wl[WSPLIT_ELEMS];

// ---------------- helpers ----------------
__device__ __forceinline__ uint32_t pack_bf2(float a, float b) {
    __nv_bfloat162 t = __floats2bfloat162_rn(a, b);
    return *(uint32_t*)&t;
}

__device__ __forceinline__ void mma16(float c[4], const uint32_t a[4], uint32_t b0, uint32_t b1) {
    asm volatile(
        "mma.sync.aligned.m16n8k16.row.col.f32.bf16.bf16.f32 "
        "{%0,%1,%2,%3},{%4,%5,%6,%7},{%8,%9},{%0,%1,%2,%3};"
        : "+f"(c[0]), "+f"(c[1]), "+f"(c[2]), "+f"(c[3])
        : "r"(a[0]), "r"(a[1]), "r"(a[2]), "r"(a[3]), "r"(b0), "r"(b1));
}

__device__ __forceinline__ void ldmx4(uint32_t d[4], const uint32_t* p) {
    uint32_t saddr = (uint32_t)__cvta_generic_to_shared(p);
    asm volatile("ldmatrix.sync.aligned.m8n8.x4.shared.b16 {%0,%1,%2,%3}, [%4];"
                 : "=r"(d[0]), "=r"(d[1]), "=r"(d[2]), "=r"(d[3]) : "r"(saddr));
}

__device__ __forceinline__ void cp_async16(const uint32_t* dst, const uint32_t* src) {
    uint32_t d = (uint32_t)__cvta_generic_to_shared(dst);
    asm volatile("cp.async.ca.shared.global [%0], [%1], 16;" :: "r"(d), "l"(src));
}

// ---------------- W bf16 hi/lo split precompute ----------------
__global__ void wsplit_kernel(const float* __restrict__ W) {
    int i = blockIdx.x * blockDim.x + threadIdx.x;
    if (i >= WSPLIT_ELEMS) return;
    int l = i / 8192;
    int rem = i - l * 8192;
    int c = rem >> 11;
    int rem2 = rem & 2047;
    int col = rem2 >> 4;
    int kp = rem2 & 15;
    int k = c * KC + 2 * kp;
    const float* Wl = W + (size_t)l * DD * DD;
    float w0 = Wl[(size_t)k * DD + col];
    float w1 = Wl[(size_t)(k + 1) * DD + col];
    uint32_t h = pack_bf2(w0, w1);
    float2 f = __bfloat1622float2(*(__nv_bfloat162*)&h);
    g_wh[i] = h;
    g_wl[i] = pack_bf2(w0 - f.x, w1 - f.y);
}

// ---------------- CSR build ----------------
__global__ void init_cnt_kernel() {
    int i = blockIdx.x * blockDim.x + threadIdx.x;
    if (i < NN) g_cnt[i] = 1;
}

__global__ void count_kernel(const int* __restrict__ ei) {
    int i = blockIdx.x * blockDim.x + threadIdx.x;
    if (i < EE) atomicAdd(&g_cnt[ei[EE + i]], 1);
}

__global__ void scan1_kernel() {
    __shared__ int sm[1024];
    int t = threadIdx.x;
    int i = blockIdx.x * 1024 + t;
    int v = (i < NN) ? g_cnt[i] : 0;
    sm[t] = v;
    __syncthreads();
#pragma unroll
    for (int o = 1; o < 1024; o <<= 1) {
        int tmp = (t >= o) ? sm[t - o] : 0;
        __syncthreads();
        sm[t] += tmp;
        __syncthreads();
    }
    if (i < NN) g_scan[i] = sm[t];
    if (t == 1023) g_bsum[blockIdx.x] = sm[t];
}

__global__ void scan2_kernel() {
    __shared__ int sm[64];
    int t = threadIdx.x;
    sm[t] = (t < NBLK_SCAN) ? g_bsum[t] : 0;
    __syncthreads();
#pragma unroll
    for (int o = 1; o < 64; o <<= 1) {
        int tmp = (t >= o) ? sm[t - o] : 0;
        __syncthreads();
        sm[t] += tmp;
        __syncthreads();
    }
    if (t < NBLK_SCAN) g_boff[t] = sm[t] - g_bsum[t];
}

__global__ void scan3_kernel() {
    int i = blockIdx.x * blockDim.x + threadIdx.x;
    if (i >= NN) return;
    int incl = g_scan[i] + g_boff[i >> 10];
    g_off[i + 1] = incl;
    g_cur[i] = incl - g_cnt[i];
    if (i == 0) g_off[0] = 0;
}

__global__ void fill_kernel(const int* __restrict__ ei) {
    int i = blockIdx.x * blockDim.x + threadIdx.x;
    if (i < EE) {
        int s = ei[i];
        int d = ei[EE + i];
        int p = atomicAdd(&g_cur[d], 1);
        g_csrc[p] = s;
    } else if (i < ET) {
        int v = i - EE;
        int p = atomicAdd(&g_cur[v], 1);
        g_csrc[p] = v;
    }
}

// ---------------- GEMM piece helpers ----------------
__device__ __forceinline__ void load_rawA(const float* __restrict__ zin,
                                          int block_row, int tid, int k0, float4 pa[4]) {
#pragma unroll
    for (int p = 0; p < 4; ++p) {
        int idx = p * 256 + tid;
        int r = idx >> 3;
        int c4 = (idx & 7) * 4;
        int gr = block_row + r;
        pa[p] = make_float4(0.f, 0.f, 0.f, 0.f);
        if (gr < NN) pa[p] = *(const float4*)(zin + (size_t)gr * DD + k0 + c4);
    }
}

__device__ __forceinline__ void storeA(uint32_t* aH, uint32_t* aL,
                                       int tid, int k0, int do_bn, const float4 pa[4]) {
#pragma unroll
    for (int p = 0; p < 4; ++p) {
        int idx = p * 256 + tid;
        int r = idx >> 3;
        int c4 = (idx & 7) * 4;
        float4 v = pa[p];
        if (do_bn) {
            float4 mu = *(const float4*)(g_mu + k0 + c4);
            float4 rs = *(const float4*)(g_rsig + k0 + c4);
            v.x = fmaxf(0.f, (v.x - mu.x) * rs.x);
            v.y = fmaxf(0.f, (v.y - mu.y) * rs.y);
            v.z = fmaxf(0.f, (v.z - mu.z) * rs.z);
            v.w = fmaxf(0.f, (v.w - mu.w) * rs.w);
        }
        uint32_t h01 = pack_bf2(v.x, v.y);
        uint32_t h23 = pack_bf2(v.z, v.w);
        float2 f01 = __bfloat1622float2(*(__nv_bfloat162*)&h01);
        float2 f23 = __bfloat1622float2(*(__nv_bfloat162*)&h23);
        uint2 hh = make_uint2(h01, h23);
        uint2 ll = make_uint2(pack_bf2(v.x - f01.x, v.y - f01.y),
                              pack_bf2(v.z - f23.x, v.w - f23.y));
        *(uint2*)&aH[r * AST + c4 / 2] = hh;
        *(uint2*)&aL[r * AST + c4 / 2] = ll;
    }
}

// ---------------- bf16 3-split GEMM, BM=128, double-buffered + cp.async B ----------------
// Epilogue stores h as fp16 (g_hf) + fused attention dots from fp32 accums.
__global__ void __launch_bounds__(256, 2) gemm_kernel(
    const float* __restrict__ zin, int layer,
    const float* __restrict__ asrc, const float* __restrict__ adst, int do_bn) {
    extern __shared__ __align__(16) uint32_t dsm[];
    uint32_t* aH = dsm;
    uint32_t* aL = aH + 2 * BUFW;
    uint32_t* bH = aL + 2 * BUFW;
    uint32_t* bL = bH + 2 * BUFW;
    float* sAS = (float*)(bL + 2 * BUFW);
    float* sAD = sAS + 256;

    int tid = threadIdx.x;
    int w = tid >> 5, lane = tid & 31;
    int wm = w & 3, wn = w >> 2;
    int block_row = blockIdx.x * 128;
    int qrow = lane >> 2, qcol = lane & 3;
    int lrow = lane & 7;
    int lsel = lane >> 3;

    const uint32_t* whL = g_wh + layer * 8192;
    const uint32_t* wlL = g_wl + layer * 8192;
    int bcol = tid >> 1;
    int bseg = (tid & 1) * 2;

    float c[2][8][4];
#pragma unroll
    for (int m = 0; m < 2; m++)
#pragma unroll
        for (int n = 0; n < 8; n++)
#pragma unroll
            for (int i = 0; i < 4; i++) c[m][n][i] = 0.f;

    float4 pa[4];

    {
        const uint32_t* srcH = whL + bcol * 16 + bseg * 4;
        const uint32_t* srcL = wlL + bcol * 16 + bseg * 4;
        cp_async16(&bH[bcol * AST + bseg * 4], srcH);
        cp_async16(&bH[bcol * AST + bseg * 4 + 4], srcH + 4);
        cp_async16(&bL[bcol * AST + bseg * 4], srcL);
        cp_async16(&bL[bcol * AST + bseg * 4 + 4], srcL + 4);
        asm volatile("cp.async.commit_group;");
        load_rawA(zin, block_row, tid, 0, pa);
        storeA(aH, aL, tid, 0, do_bn, pa);
        asm volatile("cp.async.wait_group 0;");
        __syncthreads();
    }

#pragma unroll
    for (int cc = 0; cc < 4; ++cc) {
        int cur = cc & 1;
        int nxt = cur ^ 1;
        if (cc < 3) {
            const uint32_t* srcH = whL + (cc + 1) * 2048 + bcol * 16 + bseg * 4;
            const uint32_t* srcL = wlL + (cc + 1) * 2048 + bcol * 16 + bseg * 4;
            cp_async16(&bH[nxt * BUFW + bcol * AST + bseg * 4], srcH);
            cp_async16(&bH[nxt * BUFW + bcol * AST + bseg * 4 + 4], srcH + 4);
            cp_async16(&bL[nxt * BUFW + bcol * AST + bseg * 4], srcL);
            cp_async16(&bL[nxt * BUFW + bcol * AST + bseg * 4 + 4], srcL + 4);
            asm volatile("cp.async.commit_group;");
            load_rawA(zin, block_row, tid, (cc + 1) * KC, pa);
        }

        const uint32_t* aHc = aH + cur * BUFW;
        const uint32_t* aLc = aL + cur * BUFW;
        const uint32_t* bHc = bH + cur * BUFW;
        const uint32_t* bLc = bL + cur * BUFW;
#pragma unroll
        for (int step = 0; step < 2; ++step) {
            int kq = step * 8;
            uint32_t ah[2][4], al_[2][4];
#pragma unroll
            for (int m = 0; m < 2; ++m) {
                int r = wm * 32 + m * 16 + lrow + (lsel & 1) * 8;
                int kcol = kq + (lsel >> 1) * 4;
                ldmx4(ah[m], &aHc[r * AST + kcol]);
                ldmx4(al_[m], &aLc[r * AST + kcol]);
            }
            uint32_t bh[4][4], bl_[4][4];
#pragma unroll
            for (int np = 0; np < 4; ++np) {
                int col = wn * 64 + np * 16 + lrow + (lsel >> 1) * 8;
                int kcol = kq + (lsel & 1) * 4;
                ldmx4(bh[np], &bHc[col * AST + kcol]);
                ldmx4(bl_[np], &bLc[col * AST + kcol]);
            }
#pragma unroll
            for (int np = 0; np < 4; ++np) {
#pragma unroll
                for (int sub = 0; sub < 2; ++sub) {
                    int n = np * 2 + sub;
                    uint32_t b0h = bh[np][sub * 2], b1h = bh[np][sub * 2 + 1];
                    uint32_t b0l = bl_[np][sub * 2], b1l = bl_[np][sub * 2 + 1];
                    mma16(c[0][n], ah[0], b0l, b1l);
                    mma16(c[0][n], al_[0], b0h, b1h);
                    mma16(c[0][n], ah[0], b0h, b1h);
                    mma16(c[1][n], ah[1], b0l, b1l);
                    mma16(c[1][n], al_[1], b0h, b1h);
                    mma16(c[1][n], ah[1], b0h, b1h);
                }
            }
        }
        if (cc < 3) {
            storeA(aH + nxt * BUFW, aL + nxt * BUFW, tid, (cc + 1) * KC, do_bn, pa);
            asm volatile("cp.async.wait_group 0;");
        }
        __syncthreads();
    }

    // epilogue: store h (fp16) + fused attention dots (fp32)
    float dsrc[2][2] = {{0.f, 0.f}, {0.f, 0.f}};
    float ddst[2][2] = {{0.f, 0.f}, {0.f, 0.f}};
#pragma unroll
    for (int n = 0; n < 8; ++n) {
        int col0 = wn * 64 + n * 8 + 2 * qcol;
        float as0 = asrc[col0], as1 = asrc[col0 + 1];
        float ad0 = adst[col0], ad1 = adst[col0 + 1];
#pragma unroll
        for (int m = 0; m < 2; ++m) {
            dsrc[m][0] += c[m][n][0] * as0 + c[m][n][1] * as1;
            dsrc[m][1] += c[m][n][2] * as0 + c[m][n][3] * as1;
            ddst[m][0] += c[m][n][0] * ad0 + c[m][n][1] * ad1;
            ddst[m][1] += c[m][n][2] * ad0 + c[m][n][3] * ad1;
            int row = block_row + wm * 32 + m * 16 + qrow;
            if (row < NN)
                *(__half2*)(g_hf + (size_t)row * DD + col0) =
                    __floats2half2_rn(c[m][n][0], c[m][n][1]);
            if (row + 8 < NN)
                *(__half2*)(g_hf + (size_t)(row + 8) * DD + col0) =
                    __floats2half2_rn(c[m][n][2], c[m][n][3]);
        }
    }
#pragma unroll
    for (int m = 0; m < 2; ++m)
#pragma unroll
        for (int hh = 0; hh < 2; ++hh) {
#pragma unroll
            for (int o = 1; o <= 2; o <<= 1) {
                dsrc[m][hh] += __shfl_xor_sync(0xffffffffu, dsrc[m][hh], o);
                ddst[m][hh] += __shfl_xor_sync(0xffffffffu, ddst[m][hh], o);
            }
        }
    if (qcol == 0) {
#pragma unroll
        for (int m = 0; m < 2; ++m) {
            int rl = wm * 32 + m * 16 + qrow;
            sAS[wn * 128 + rl] = dsrc[m][0];
            sAS[wn * 128 + rl + 8] = dsrc[m][1];
            sAD[wn * 128 + rl] = ddst[m][0];
            sAD[wn * 128 + rl + 8] = ddst[m][1];
        }
    }
    __syncthreads();
    if (tid < 128) {
        int gr = block_row + tid;
        if (gr < NN) {
            g_as[gr] = sAS[tid] + sAS[128 + tid];
            g_ad[gr] = sAD[tid] + sAD[128 + tid];
        }
    }
}

// ------- fused softmax + gather (fp16 h) + BN partials: 8 warps = 8 nodes/block -------
__global__ void __launch_bounds__(256) aggregate_kernel(
    const float* __restrict__ bias, float* __restrict__ zout) {
    int n = (blockIdx.x * blockDim.x + threadIdx.x) >> 5;
    int w = threadIdx.x >> 5;
    int lane = threadIdx.x & 31;

    __shared__ float sredS[8][DD];
    __shared__ float sredQ[8][DD];

    const __half* hf = g_hf;
    float4 ov = make_float4(0.f, 0.f, 0.f, 0.f);
    if (n < NN) {
        int beg = g_off[n], end = g_off[n + 1];
        float adn = g_ad[n];
        float4 acc = make_float4(0.f, 0.f, 0.f, 0.f);
        float psum = 0.f;
        int j = beg;
        for (; j + 8 <= end; j += 8) {
            int s0 = __ldg(&g_csrc[j + 0]);
            int s1 = __ldg(&g_csrc[j + 1]);
            int s2 = __ldg(&g_csrc[j + 2]);
            int s3 = __ldg(&g_csrc[j + 3]);
            int s4 = __ldg(&g_csrc[j + 4]);
            int s5 = __ldg(&g_csrc[j + 5]);
            int s6 = __ldg(&g_csrc[j + 6]);
            int s7 = __ldg(&g_csrc[j + 7]);
            float e0 = __ldg(&g_as[s0]) + adn;
            float e1 = __ldg(&g_as[s1]) + adn;
            float e2 = __ldg(&g_as[s2]) + adn;
            float e3 = __ldg(&g_as[s3]) + adn;
            float e4 = __ldg(&g_as[s4]) + adn;
            float e5 = __ldg(&g_as[s5]) + adn;
            float e6 = __ldg(&g_as[s6]) + adn;
            float e7 = __ldg(&g_as[s7]) + adn;
            e0 = (e0 > 0.f) ? e0 : SLOPE * e0;
            e1 = (e1 > 0.f) ? e1 : SLOPE * e1;
            e2 = (e2 > 0.f) ? e2 : SLOPE * e2;
            e3 = (e3 > 0.f) ? e3 : SLOPE * e3;
            e4 = (e4 > 0.f) ? e4 : SLOPE * e4;
            e5 = (e5 > 0.f) ? e5 : SLOPE * e5;
            e6 = (e6 > 0.f) ? e6 : SLOPE * e6;
            e7 = (e7 > 0.f) ? e7 : SLOPE * e7;
            float p0 = __expf(e0), p1 = __expf(e1), p2 = __expf(e2), p3 = __expf(e3);
            float p4 = __expf(e4), p5 = __expf(e5), p6 = __expf(e6), p7 = __expf(e7);
            uint2 u0 = __ldg((const uint2*)(hf + (size_t)s0 * DD + lane * 4));
            uint2 u1 = __ldg((const uint2*)(hf + (size_t)s1 * DD + lane * 4));
            uint2 u2 = __ldg((const uint2*)(hf + (size_t)s2 * DD + lane * 4));
            uint2 u3 = __ldg((const uint2*)(hf + (size_t)s3 * DD + lane * 4));
            uint2 u4 = __ldg((const uint2*)(hf + (size_t)s4 * DD + lane * 4));
            uint2 u5 = __ldg((const uint2*)(hf + (size_t)s5 * DD + lane * 4));
            uint2 u6 = __ldg((const uint2*)(hf + (size_t)s6 * DD + lane * 4));
            uint2 u7 = __ldg((const uint2*)(hf + (size_t)s7 * DD + lane * 4));
#define ACCUM(ux, px)                                                    \
            {                                                            \
                float2 fa = __half22float2(*(__half2*)&ux.x);            \
                float2 fb = __half22float2(*(__half2*)&ux.y);            \
                acc.x += px * fa.x;                                      \
                acc.y += px * fa.y;                                      \
                acc.z += px * fb.x;                                      \
                acc.w += px * fb.y;                                      \
            }
            ACCUM(u0, p0) ACCUM(u1, p1) ACCUM(u2, p2) ACCUM(u3, p3)
            ACCUM(u4, p4) ACCUM(u5, p5) ACCUM(u6, p6) ACCUM(u7, p7)
            psum += p0 + p1 + p2 + p3 + p4 + p5 + p6 + p7;
        }
        for (; j < end; ++j) {
            int s0 = __ldg(&g_csrc[j]);
            float e0 = __ldg(&g_as[s0]) + adn;
            e0 = (e0 > 0.f) ? e0 : SLOPE * e0;
            float p0 = __expf(e0);
            uint2 u0 = __ldg((const uint2*)(hf + (size_t)s0 * DD + lane * 4));
            ACCUM(u0, p0)
            psum += p0;
        }
#undef ACCUM
        float rinv = 1.f / psum;
        float4 bv = *(const float4*)(bias + lane * 4);
        ov = make_float4(acc.x * rinv + bv.x, acc.y * rinv + bv.y,
                         acc.z * rinv + bv.z, acc.w * rinv + bv.w);
        *(float4*)(zout + (size_t)n * DD + lane * 4) = ov;
    }
    *(float4*)&sredS[w][lane * 4] = ov;
    *(float4*)&sredQ[w][lane * 4] =
        make_float4(ov.x * ov.x, ov.y * ov.y, ov.z * ov.z, ov.w * ov.w);
    __syncthreads();
    int t = threadIdx.x;
    if (t < DD) {
        float s = 0.f, q = 0.f;
#pragma unroll
        for (int ww = 0; ww < 8; ++ww) {
            s += sredS[ww][t];
            q += sredQ[ww][t];
        }
        g_psumf[(size_t)blockIdx.x * DD + t] = s;
        g_psqf[(size_t)blockIdx.x * DD + t] = q;
    }
}

// ---------------- BN stats final reduce ----------------
__global__ void reduce_stats_kernel() {
    int d = blockIdx.x;
    int t = threadIdx.x;
    double s = 0.0, q = 0.0;
    for (int b = t; b < NBLK_AGG; b += 256) {
        s += (double)g_psumf[(size_t)b * DD + d];
        q += (double)g_psqf[(size_t)b * DD + d];
    }
    __shared__ double shs[256], shq[256];
    shs[t] = s;
    shq[t] = q;
    __syncthreads();
#pragma unroll
    for (int o = 128; o > 0; o >>= 1) {
        if (t < o) {
            shs[t] += shs[t + o];
            shq[t] += shq[t + o];
        }
        __syncthreads();
    }
    if (t == 0) {
        double mu = shs[0] / (double)NN;
        double var = shq[0] / (double)NN - mu * mu;
        g_mu[d] = (float)mu;
        g_rsig[d] = (float)(1.0 / sqrt(var + 1e-5));
    }
}

__global__ void bn_apply_kernel(const float* __restrict__ zin, float* __restrict__ zo) {
    int i = blockIdx.x * blockDim.x + threadIdx.x;
    if (i >= NN * DD) return;
    int d = i & 127;
    float v = (zin[i] - g_mu[d]) * g_rsig[d];
    zo[i] = (v > 0.f) ? v : 0.f;
}

// ---------------- launch ----------------
extern "C" void kernel_launch(void* const* d_in, const int* in_sizes, int n_in,
                              void* d_out, int out_size) {
    const float* x = (const float*)d_in[0];
    const int* ei = (const int*)d_in[1];
    const float* W = (const float*)d_in[2];
    const float* a_src = (const float*)d_in[3];
    const float* a_dst = (const float*)d_in[4];
    const float* b = (const float*)d_in[5];
    float* out = (float*)d_out;

    float* zptr = nullptr;
    cudaGetSymbolAddress((void**)&zptr, g_z);

    static cudaStream_t s2 = nullptr;
    static cudaEvent_t ev_fork = nullptr, ev_join = nullptr;
    if (!s2) {
        cudaStreamCreateWithFlags(&s2, cudaStreamNonBlocking);
        cudaEventCreateWithFlags(&ev_fork, cudaEventDisableTiming);
        cudaEventCreateWithFlags(&ev_join, cudaEventDisableTiming);
        cudaFuncSetAttribute(gemm_kernel, cudaFuncAttributeMaxDynamicSharedMemorySize,
                             SMEM_BYTES_G);
    }

    cudaEventRecord(ev_fork, 0);
    cudaStreamWaitEvent(s2, ev_fork, 0);

    wsplit_kernel<<<(WSPLIT_ELEMS + 255) / 256, 256, 0, s2>>>(W);
    init_cnt_kernel<<<(NN + 255) / 256, 256>>>();
    count_kernel<<<(EE + 255) / 256, 256>>>(ei);
    scan1_kernel<<<NBLK_SCAN, 1024>>>();
    gemm_kernel<<<(NN + 127) / 128, 256, SMEM_BYTES_G, s2>>>(x, 0, a_src, a_dst, 0);
    scan2_kernel<<<1, 64>>>();
    scan3_kernel<<<(NN + 255) / 256, 256>>>();
    fill_kernel<<<(ET + 255) / 256, 256>>>(ei);

    cudaEventRecord(ev_join, s2);
    cudaStreamWaitEvent(0, ev_join, 0);

    for (int l = 0; l < LL; ++l) {
        if (l > 0)
            gemm_kernel<<<(NN + 127) / 128, 256, SMEM_BYTES_G>>>(
                zptr, l, a_src + l * DD, a_dst + l * DD, 1);
        aggregate_kernel<<<NBLK_AGG, 256>>>(b + l * DD, zptr);
        reduce_stats_kernel<<<DD, 256>>>();
    }
    bn_apply_kernel<<<(NN * DD + 255) / 256, 256>>>(zptr, out);
}